// round 7
// baseline (speedup 1.0000x reference)
#include <cuda_runtime.h>
#include <math.h>
#include <stdint.h>

#define NTS      4096
#define SEQ_LEN  168
#define HORIZON  24
#define TTOT     (SEQ_LEN + HORIZON)
#define F_IN     32
#define EMBED    32
#define HIDDEN   64
#define LAYERS   2

#define BLK      256
#define GRID_B   512                     /* 512 x 8 warps = 4096 series */
#define NCTA_A   (NTS * SEQ_LEN / 128)   /* 5376 CTAs x 128 items */

/* ---- smem byte offsets (union of A and B roles) ---- */
#define OFF_W       0                    /* A: packed W pairs; B: transposed WT (98304 B) */
#define OFF_BP      98304                /* A: packed bias pairs u64[2][96]   (1536 B) */
#define OFF_SB      99840                /* B: scalar biases float[2][192]    (1536 B) */
#define OFF_SWE     101376
#define OFF_SBE     101504
#define OFF_SWMU    101632
#define OFF_SWSG    101888
#define OFF_H0      102144               /* A: 2 x [64][128] float; B: sH 8x64 */
#define SMEM_TOTAL  (102144 + 65536)

typedef unsigned long long u64;

__device__ __forceinline__ float ex2f(float x) {
    float r; asm("ex2.approx.f32 %0, %1;" : "=f"(r) : "f"(x)); return r;
}
__device__ __forceinline__ float rcpf(float x) {
    float r; asm("rcp.approx.f32 %0, %1;" : "=f"(r) : "f"(x)); return r;
}
__device__ __forceinline__ float sigm(float x) {
    return rcpf(1.0f + ex2f(-1.4426950408889634f * x));
}
__device__ __forceinline__ float tanh_(float x) {
    return 1.0f - 2.0f * rcpf(1.0f + ex2f(2.8853900817779268f * x));
}
__device__ __forceinline__ float softplus_(float x) {
    return (x > 20.0f) ? x : log1pf(ex2f(1.4426950408889634f * x));
}
__device__ __forceinline__ int src_row(int r) { return r + ((r >= 64) ? 64 : 0); }

__device__ __forceinline__ u64 pack2(float lo, float hi) {
    u64 r; asm("mov.b64 %0, {%1,%2};" : "=l"(r) : "f"(lo), "f"(hi)); return r;
}
__device__ __forceinline__ void unpack2(u64 v, float& a, float& b) {
    asm("mov.b64 {%0,%1}, %2;" : "=f"(a), "=f"(b) : "l"(v));
}
__device__ __forceinline__ u64 ffma2(u64 a, u64 b, u64 c) {
    u64 d; asm("fma.rn.f32x2 %0, %1, %2, %3;" : "=l"(d) : "l"(a), "l"(b), "l"(c));
    return d;
}

/* ------------- phase-A GEMM layer: [128 m x 192 j] = Hin^T @ W^T ----------
   warp wid owns j-pairs [wid*4, wid*4+4) x 3 gates; lane owns m = lane*4..+3.
   Weights pre-packed: Wp[k][g][jp] = (W[j0][k], W[j1][k]) as u64.            */
__device__ __forceinline__ void gemm_layer(const u64* __restrict__ Wp,
                                           const u64* __restrict__ BP,
                                           const float* __restrict__ Hin,
                                           float* __restrict__ Hout,
                                           int wid, int lane, int relu_out)
{
    u64 acc[3][4][4];
    #pragma unroll
    for (int g = 0; g < 3; ++g)
        #pragma unroll
        for (int jp = 0; jp < 4; ++jp) {
            u64 b = BP[g * 32 + wid * 4 + jp];
            #pragma unroll
            for (int mi = 0; mi < 4; ++mi) acc[g][jp][mi] = b;
        }

    #pragma unroll 4
    for (int k = 0; k < 64; ++k) {
        const u64* wrow = Wp + k * 96 + wid * 4;
        u64 wg[3][4];
        #pragma unroll
        for (int g = 0; g < 3; ++g) {
            ulonglong2 t0 = *(const ulonglong2*)(wrow + g * 32);
            ulonglong2 t1 = *(const ulonglong2*)(wrow + g * 32 + 2);
            wg[g][0] = t0.x; wg[g][1] = t0.y; wg[g][2] = t1.x; wg[g][3] = t1.y;
        }
        float4 hv = *(const float4*)(Hin + k * 128 + lane * 4);
        u64 hh[4];
        hh[0] = pack2(hv.x, hv.x); hh[1] = pack2(hv.y, hv.y);
        hh[2] = pack2(hv.z, hv.z); hh[3] = pack2(hv.w, hv.w);
        #pragma unroll
        for (int g = 0; g < 3; ++g)
            #pragma unroll
            for (int jp = 0; jp < 4; ++jp)
                #pragma unroll
                for (int mi = 0; mi < 4; ++mi)
                    acc[g][jp][mi] = ffma2(wg[g][jp], hh[mi], acc[g][jp][mi]);
    }

    #pragma unroll
    for (int jp = 0; jp < 4; ++jp) {
        const int j0 = (wid * 4 + jp) * 2;
        #pragma unroll
        for (int mi = 0; mi < 4; ++mi) {
            float i0, i1, g0, g1, o0, o1;
            unpack2(acc[0][jp][mi], i0, i1);
            unpack2(acc[1][jp][mi], g0, g1);
            unpack2(acc[2][jp][mi], o0, o1);
            float c0 = sigm(i0) * tanh_(g0);
            float h0 = sigm(o0) * tanh_(c0);
            float c1 = sigm(i1) * tanh_(g1);
            float h1 = sigm(o1) * tanh_(c1);
            if (relu_out) { h0 = fmaxf(h0, 0.0f); h1 = fmaxf(h1, 0.0f); }
            const int m = lane * 4 + mi;
            Hout[j0 * 128 + m]       = h0;
            Hout[(j0 + 1) * 128 + m] = h1;
        }
    }
}

__global__ void __launch_bounds__(BLK, 1) deepar_v5(
    const float* __restrict__ X, const float* __restrict__ y,
    const float* __restrict__ Xf,
    const float* __restrict__ W_embed, const float* __restrict__ b_embed,
    const float* __restrict__ W_ih, const float* __restrict__ b_ih,
    const float* __restrict__ b_hh,
    const float* __restrict__ W_mu, const float* __restrict__ b_mu,
    const float* __restrict__ W_sigma, const float* __restrict__ b_sigma,
    float* __restrict__ out)
{
    extern __shared__ char sm[];
    float* sWe  = (float*)(sm + OFF_SWE);
    float* sBe  = (float*)(sm + OFF_SBE);
    float* sWmu = (float*)(sm + OFF_SWMU);
    float* sWsg = (float*)(sm + OFF_SWSG);

    const int tid  = threadIdx.x;
    const int lane = tid & 31;
    const int wid  = tid >> 5;
    const bool isB = (blockIdx.x < GRID_B);

    float* out_mu = out + NTS * HORIZON;
    float* out_sg = out_mu + NTS * TTOT;

    if (tid < 32) { sWe[tid] = W_embed[tid]; sBe[tid] = b_embed[tid]; }
    if (tid < 64) { sWmu[tid] = W_mu[tid]; sWsg[tid] = W_sigma[tid]; }

    if (isB) {
        /* ============ Phase B: horizon scan, 8 warps = 8 series ========== */
        float* sWT = (float*)(sm + OFF_W);      /* [2][64][192] transposed */
        float* sB  = (float*)(sm + OFF_SB);
        for (int idx = tid; idx < 2 * 192 * 64; idx += BLK) {
            int l = idx / 12288, rem = idx % 12288;
            int r = rem / 64, k = rem % 64;
            sWT[l * 12288 + k * 192 + r] = W_ih[l * 16384 + src_row(r) * 64 + k];
        }
        for (int idx = tid; idx < 2 * 192; idx += BLK) {
            int l = idx / 192, r = idx % 192;
            int sr = l * 256 + src_row(r);
            sB[idx] = b_ih[sr] + b_hh[sr];
        }
        __syncthreads();

        const int n = blockIdx.x * 8 + wid;
        float* sh = (float*)(sm + OFF_H0) + wid * 64;
        const float bmu = b_mu[0], bsg = b_sigma[0];
        const float we = sWe[lane], be = sBe[lane];
        const float wmu0 = sWmu[lane], wmu1 = sWmu[32 + lane];
        const float wsg0 = sWsg[lane], wsg1 = sWsg[32 + lane];

        float carry = 0.0f;
        for (int sp = 0; sp <= HORIZON; ++sp) {
            const bool seed = (sp == 0);
            const float yn = seed ? y[(size_t)n * SEQ_LEN + (SEQ_LEN - 1)] : carry;
            const float* xsrc = seed
                ? (X + ((size_t)n * SEQ_LEN + (SEQ_LEN - 1)) * F_IN)
                : (Xf + ((size_t)n * HORIZON + (sp - 1)) * F_IN);

            sh[lane]      = xsrc[lane];
            sh[32 + lane] = fmaf(yn, we, be);
            __syncwarp();

            #pragma unroll
            for (int l = 0; l < LAYERS; ++l) {
                const float* WT = sWT + l * 12288;
                const float* Bb = sB + l * 192;
                float a0 = Bb[lane],      a1 = Bb[64 + lane],  a2 = Bb[128 + lane];
                float a3 = Bb[32 + lane], a4 = Bb[96 + lane],  a5 = Bb[160 + lane];
                #pragma unroll
                for (int k = 0; k < 64; ++k) {
                    const float hk = sh[k];
                    const float* row = WT + k * 192;
                    a0 = fmaf(row[lane],       hk, a0);
                    a1 = fmaf(row[64 + lane],  hk, a1);
                    a2 = fmaf(row[128 + lane], hk, a2);
                    a3 = fmaf(row[32 + lane],  hk, a3);
                    a4 = fmaf(row[96 + lane],  hk, a4);
                    a5 = fmaf(row[160 + lane], hk, a5);
                }
                float c0 = sigm(a0) * tanh_(a1);
                float h0 = sigm(a2) * tanh_(c0);
                float c1 = sigm(a3) * tanh_(a4);
                float h1 = sigm(a5) * tanh_(c1);
                __syncwarp();
                sh[lane] = h0; sh[32 + lane] = h1;
                __syncwarp();
            }

            float r0 = fmaxf(sh[lane], 0.0f), r1 = fmaxf(sh[32 + lane], 0.0f);
            float pm = r0 * wmu0 + r1 * wmu1;
            float ps = r0 * wsg0 + r1 * wsg1;
            #pragma unroll
            for (int off = 16; off; off >>= 1) {
                pm += __shfl_xor_sync(0xFFFFFFFFu, pm, off);
                ps += __shfl_xor_sync(0xFFFFFFFFu, ps, off);
            }
            float mu = pm + bmu;
            float sigma = softplus_(ps + bsg) + 1e-6f;
            float s2 = sigma * sigma;
            float d = yn - mu;
            float lik = rsqrtf(2.0f * (float)M_PI * s2) *
                        ex2f(-1.4426950408889634f * (d * d) / (2.0f * s2));

            if (lane == 0) {
                if (seed) {
                    out[n * HORIZON] = lik;
                } else {
                    const int t = SEQ_LEN + sp - 1;
                    out_mu[n * TTOT + t] = mu;
                    out_sg[n * TTOT + t] = sigma;
                    if (sp <= HORIZON - 1) out[n * HORIZON + sp] = lik;
                }
            }
            carry = lik;
        }
        return;
    }

    /* ================= Phase A: register-tiled GEMM ====================== */
    u64*   Wp = (u64*)(sm + OFF_W);     /* [2][64][3][32] packed j-pairs */
    u64*   BP = (u64*)(sm + OFF_BP);    /* [2][3][32] packed bias pairs */
    float* H0 = (float*)(sm + OFF_H0);  /* [64][128] */
    float* H1 = H0 + 64 * 128;

    const int aBase = (blockIdx.x - GRID_B) * 128;

    for (int idx = tid; idx < 2 * 64 * 96; idx += BLK) {
        int l = idx / 6144, rem = idx % 6144;
        int k = rem / 96, r2 = rem % 96;
        int g = r2 / 32, jp = r2 % 32;
        int srow = ((g == 0) ? 0 : (g == 1) ? 128 : 192) + 2 * jp;
        const float* wl_ = W_ih + l * 16384 + srow * 64 + k;
        Wp[idx] = pack2(wl_[0], wl_[64]);
    }
    for (int idx = tid; idx < 2 * 96; idx += BLK) {
        int l = idx / 96, r2 = idx % 96;
        int g = r2 / 32, jp = r2 % 32;
        int srow = l * 256 + ((g == 0) ? 0 : (g == 1) ? 128 : 192) + 2 * jp;
        BP[idx] = pack2(b_ih[srow] + b_hh[srow],
                        b_ih[srow + 1] + b_hh[srow + 1]);
    }

    /* H0 rows 0..31 = X features (coalesced loads, transpose via STS) */
    #pragma unroll
    for (int p = 0; p < 4; ++p) {
        int m  = p * 32 + (tid >> 3);
        int f4 = tid & 7;
        float4 v = ((const float4*)X)[(size_t)(aBase + m) * 8 + f4];
        H0[(f4 * 4 + 0) * 128 + m] = v.x;
        H0[(f4 * 4 + 1) * 128 + m] = v.y;
        H0[(f4 * 4 + 2) * 128 + m] = v.z;
        H0[(f4 * 4 + 3) * 128 + m] = v.w;
    }
    /* H0 rows 32..63 = y embed */
    for (int idx = tid; idx < 32 * 128; idx += BLK) {
        int e = idx >> 7, m = idx & 127;
        H0[(32 + e) * 128 + m] = fmaf(y[aBase + m], W_embed[e], b_embed[e]);
    }
    __syncthreads();

    gemm_layer(Wp, BP, H0, H1, wid, lane, 0);
    __syncthreads();
    gemm_layer(Wp + 6144, BP + 96, H1, H0, wid, lane, 1);
    __syncthreads();

    /* head: 2 threads per item */
    {
        const int m = tid >> 1, sub = tid & 1;
        float pm = 0.0f, ps = 0.0f;
        #pragma unroll
        for (int jj = 0; jj < 32; ++jj) {
            int j = sub * 32 + jj;
            float r = H0[j * 128 + m];
            pm = fmaf(r, sWmu[j], pm);
            ps = fmaf(r, sWsg[j], ps);
        }
        pm += __shfl_xor_sync(0xFFFFFFFFu, pm, 1);
        ps += __shfl_xor_sync(0xFFFFFFFFu, ps, 1);
        if (sub == 0) {
            const int item = aBase + m;
            const int n = item / SEQ_LEN, t = item % SEQ_LEN;
            float mu = pm + b_mu[0];
            float sigma = softplus_(ps + b_sigma[0]) + 1e-6f;
            out_mu[n * TTOT + t] = mu;
            out_sg[n * TTOT + t] = sigma;
        }
    }
}

extern "C" void kernel_launch(void* const* d_in, const int* in_sizes, int n_in,
                              void* d_out, int out_size)
{
    const float* X       = (const float*)d_in[0];
    const float* y       = (const float*)d_in[1];
    const float* Xf      = (const float*)d_in[2];
    const float* W_embed = (const float*)d_in[3];
    const float* b_embed = (const float*)d_in[4];
    const float* W_ih    = (const float*)d_in[5];
    const float* b_ih    = (const float*)d_in[6];
    const float* b_hh    = (const float*)d_in[7];
    const float* W_mu    = (const float*)d_in[8];
    const float* b_mu    = (const float*)d_in[9];
    const float* W_sigma = (const float*)d_in[10];
    const float* b_sigma = (const float*)d_in[11];
    float* out = (float*)d_out;

    static bool attr_done = false;
    if (!attr_done) {
        cudaFuncSetAttribute(deepar_v5,
            cudaFuncAttributeMaxDynamicSharedMemorySize, SMEM_TOTAL);
        attr_done = true;
    }

    deepar_v5<<<GRID_B + NCTA_A, BLK, SMEM_TOTAL>>>(
        X, y, Xf, W_embed, b_embed, W_ih, b_ih, b_hh,
        W_mu, b_mu, W_sigma, b_sigma, out);
}

// round 11
// speedup vs baseline: 1.3146x; 1.3146x over previous
#include <cuda_runtime.h>
#include <cuda_fp16.h>
#include <math.h>
#include <stdint.h>

#define NTS      4096
#define SEQ_LEN  168
#define HORIZON  24
#define TTOT     (SEQ_LEN + HORIZON)
#define F_IN     32
#define EMBED    32
#define HIDDEN   64
#define LAYERS   2

#define BLK      128
#define GRID_B   1024                    /* 1024 x 4 warps = 4096 series */
#define NCTA_A   (NTS * SEQ_LEN / 256)   /* 2688 CTAs x 256 items (2/thread) */

/* ---- smem byte offsets ---- */
#define OFF_W       0                    /* A: [2][192][64] row-major; B: WT transposed */
#define OFF_SB      98304                /* float[2][192] combined biases */
#define OFF_SWE     99840
#define OFF_SBE     99968
#define OFF_SWMU    100096
#define OFF_SWSG    100352
#define OFF_SH      100608               /* B role: 4 warps x 64 floats */
#define SMEM_TOTAL  (100608 + 1024)

typedef unsigned long long u64;

__device__ __forceinline__ float ex2f(float x) {
    float r; asm("ex2.approx.f32 %0, %1;" : "=f"(r) : "f"(x)); return r;
}
__device__ __forceinline__ float rcpf(float x) {
    float r; asm("rcp.approx.f32 %0, %1;" : "=f"(r) : "f"(x)); return r;
}
__device__ __forceinline__ float sigm(float x) {
    return rcpf(1.0f + ex2f(-1.4426950408889634f * x));
}
__device__ __forceinline__ float tanh_(float x) {
    return 1.0f - 2.0f * rcpf(1.0f + ex2f(2.8853900817779268f * x));
}
__device__ __forceinline__ float softplus_(float x) {
    return (x > 20.0f) ? x : log1pf(ex2f(1.4426950408889634f * x));
}
__device__ __forceinline__ int src_row(int r) { return r + ((r >= 64) ? 64 : 0); }

__device__ __forceinline__ u64 pack2(float lo, float hi) {
    u64 r; asm("mov.b64 %0, {%1,%2};" : "=l"(r) : "f"(lo), "f"(hi)); return r;
}
__device__ __forceinline__ void unpack2(u64 v, float& a, float& b) {
    asm("mov.b64 {%0,%1}, %2;" : "=f"(a), "=f"(b) : "l"(v));
}
__device__ __forceinline__ u64 ffma2(u64 a, u64 b, u64 c) {
    u64 d; asm("fma.rn.f32x2 %0, %1, %2, %3;" : "=l"(d) : "l"(a), "l"(b), "l"(c));
    return d;
}

__global__ void __launch_bounds__(BLK, 1) deepar_v8(
    const float* __restrict__ X, const float* __restrict__ y,
    const float* __restrict__ Xf,
    const float* __restrict__ W_embed, const float* __restrict__ b_embed,
    const float* __restrict__ W_ih, const float* __restrict__ b_ih,
    const float* __restrict__ b_hh,
    const float* __restrict__ W_mu, const float* __restrict__ b_mu,
    const float* __restrict__ W_sigma, const float* __restrict__ b_sigma,
    float* __restrict__ out)
{
    extern __shared__ char sm[];
    float* sB   = (float*)(sm + OFF_SB);
    float* sWe  = (float*)(sm + OFF_SWE);
    float* sBe  = (float*)(sm + OFF_SBE);
    float* sWmu = (float*)(sm + OFF_SWMU);
    float* sWsg = (float*)(sm + OFF_SWSG);

    const int tid  = threadIdx.x;
    const int lane = tid & 31;
    const int wid  = tid >> 5;
    const bool isB = (blockIdx.x < GRID_B);

    float* out_mu = out + NTS * HORIZON;
    float* out_sg = out_mu + NTS * TTOT;

    /* biases + small weights */
    for (int idx = tid; idx < 2 * 192; idx += BLK) {
        int l = idx / 192, r = idx % 192;
        int sr = l * 256 + src_row(r);
        sB[idx] = b_ih[sr] + b_hh[sr];
    }
    if (tid < 32) { sWe[tid] = W_embed[tid]; sBe[tid] = b_embed[tid]; }
    if (tid < 64) { sWmu[tid] = W_mu[tid]; sWsg[tid] = W_sigma[tid]; }

    if (isB) {
        /* ============ Phase B: horizon scan, 4 warps = 4 series ========== */
        float* sWT = (float*)(sm + OFF_W);      /* [2][64][192] transposed */
        for (int idx = tid; idx < 2 * 192 * 64; idx += BLK) {
            int l = idx / 12288, rem = idx % 12288;
            int r = rem / 64, k = rem % 64;
            sWT[l * 12288 + k * 192 + r] = W_ih[l * 16384 + src_row(r) * 64 + k];
        }
        __syncthreads();

        const int n = blockIdx.x * 4 + wid;
        float* sh = (float*)(sm + OFF_SH) + wid * 64;
        const float bmu = b_mu[0], bsg = b_sigma[0];
        const float we = sWe[lane], be = sBe[lane];
        const float wmu0 = sWmu[lane], wmu1 = sWmu[32 + lane];
        const float wsg0 = sWsg[lane], wsg1 = sWsg[32 + lane];

        float carry = 0.0f;
        for (int sp = 0; sp <= HORIZON; ++sp) {
            const bool seed = (sp == 0);
            const float yn = seed ? y[(size_t)n * SEQ_LEN + (SEQ_LEN - 1)] : carry;
            const float* xsrc = seed
                ? (X + ((size_t)n * SEQ_LEN + (SEQ_LEN - 1)) * F_IN)
                : (Xf + ((size_t)n * HORIZON + (sp - 1)) * F_IN);

            sh[lane]      = xsrc[lane];
            sh[32 + lane] = fmaf(yn, we, be);
            __syncwarp();

            #pragma unroll
            for (int l = 0; l < LAYERS; ++l) {
                const float* WT = sWT + l * 12288;
                const float* Bb = sB + l * 192;
                float a0 = Bb[lane],      a1 = Bb[64 + lane],  a2 = Bb[128 + lane];
                float a3 = Bb[32 + lane], a4 = Bb[96 + lane],  a5 = Bb[160 + lane];
                #pragma unroll
                for (int k = 0; k < 64; ++k) {
                    const float hk = sh[k];
                    const float* row = WT + k * 192;
                    a0 = fmaf(row[lane],       hk, a0);
                    a1 = fmaf(row[64 + lane],  hk, a1);
                    a2 = fmaf(row[128 + lane], hk, a2);
                    a3 = fmaf(row[32 + lane],  hk, a3);
                    a4 = fmaf(row[96 + lane],  hk, a4);
                    a5 = fmaf(row[160 + lane], hk, a5);
                }
                float c0 = sigm(a0) * tanh_(a1);
                float h0 = sigm(a2) * tanh_(c0);
                float c1 = sigm(a3) * tanh_(a4);
                float h1 = sigm(a5) * tanh_(c1);
                __syncwarp();
                sh[lane] = h0; sh[32 + lane] = h1;
                __syncwarp();
            }

            float r0 = fmaxf(sh[lane], 0.0f), r1 = fmaxf(sh[32 + lane], 0.0f);
            float pm = r0 * wmu0 + r1 * wmu1;
            float ps = r0 * wsg0 + r1 * wsg1;
            #pragma unroll
            for (int off = 16; off; off >>= 1) {
                pm += __shfl_xor_sync(0xFFFFFFFFu, pm, off);
                ps += __shfl_xor_sync(0xFFFFFFFFu, ps, off);
            }
            float mu = pm + bmu;
            float sigma = softplus_(ps + bsg) + 1e-6f;
            float s2 = sigma * sigma;
            float d = yn - mu;
            float lik = rsqrtf(2.0f * (float)M_PI * s2) *
                        ex2f(-1.4426950408889634f * (d * d) / (2.0f * s2));

            if (lane == 0) {
                if (seed) {
                    out[n * HORIZON] = lik;
                } else {
                    const int t = SEQ_LEN + sp - 1;
                    out_mu[n * TTOT + t] = mu;
                    out_sg[n * TTOT + t] = sigma;
                    if (sp <= HORIZON - 1) out[n * HORIZON + sp] = lik;
                }
            }
            carry = lik;
        }
        return;
    }

    /* ============ Phase A: 2 items per thread, h in registers ============ */
    float* sW = (float*)(sm + OFF_W);   /* [2][192][64] row-major i,g,o */
    for (int idx = tid; idx < 2 * 192 * 64; idx += BLK) {
        int l = idx / 12288, rem = idx % 12288;
        int r = rem / 64, k = rem % 64;
        sW[idx] = W_ih[l * 16384 + src_row(r) * 64 + k];
    }
    __syncthreads();

    const int aBase = (blockIdx.x - GRID_B) * 256;
    const int mA = aBase + tid;
    const int mB = aBase + 128 + tid;

    /* h packed per item over k-pairs: h2A[kp] = (hA[2kp], hA[2kp+1]) */
    u64 h2A[32], h2B[32];
    {
        const float4* xa = (const float4*)(X + (size_t)mA * F_IN);
        const float4* xb = (const float4*)(X + (size_t)mB * F_IN);
        #pragma unroll
        for (int q = 0; q < 8; ++q) {
            float4 va = xa[q], vb = xb[q];
            h2A[2 * q]     = pack2(va.x, va.y);
            h2A[2 * q + 1] = pack2(va.z, va.w);
            h2B[2 * q]     = pack2(vb.x, vb.y);
            h2B[2 * q + 1] = pack2(vb.z, vb.w);
        }
        const float ynA = y[mA], ynB = y[mB];
        #pragma unroll
        for (int e = 0; e < 16; ++e) {
            float w0 = sWe[2 * e], w1 = sWe[2 * e + 1];
            float b0 = sBe[2 * e], b1 = sBe[2 * e + 1];
            h2A[16 + e] = pack2(fmaf(ynA, w0, b0), fmaf(ynA, w1, b1));
            h2B[16 + e] = pack2(fmaf(ynB, w0, b0), fmaf(ynB, w1, b1));
        }
    }

    /* ---------------- layer 1 -> hn16[j] = half2(hA[j], hB[j]) ---------- */
    uint32_t hn16[64];
    {
        const float* W = sW;
        const float* Bb = sB;
        #pragma unroll 1
        for (int j = 0; j < 64; ++j) {
            const ulonglong2* wi = (const ulonglong2*)(W + j * 64);
            const ulonglong2* wg = (const ulonglong2*)(W + (64 + j) * 64);
            const ulonglong2* wo = (const ulonglong2*)(W + (128 + j) * 64);
            u64 aiA = pack2(Bb[j], 0.f),       aiB = aiA;
            u64 agA = pack2(Bb[64 + j], 0.f),  agB = agA;
            u64 aoA = pack2(Bb[128 + j], 0.f), aoB = aoA;
            #pragma unroll
            for (int q = 0; q < 16; ++q) {
                ulonglong2 vi = wi[q], vg = wg[q], vo = wo[q];
                u64 a0 = h2A[2 * q], a1 = h2A[2 * q + 1];
                u64 b0 = h2B[2 * q], b1 = h2B[2 * q + 1];
                aiA = ffma2(vi.x, a0, aiA); aiB = ffma2(vi.x, b0, aiB);
                agA = ffma2(vg.x, a0, agA); agB = ffma2(vg.x, b0, agB);
                aoA = ffma2(vo.x, a0, aoA); aoB = ffma2(vo.x, b0, aoB);
                aiA = ffma2(vi.y, a1, aiA); aiB = ffma2(vi.y, b1, aiB);
                agA = ffma2(vg.y, a1, agA); agB = ffma2(vg.y, b1, agB);
                aoA = ffma2(vo.y, a1, aoA); aoB = ffma2(vo.y, b1, aoB);
            }
            float x0, x1, g0, g1, o0, o1;
            unpack2(aiA, x0, x1); unpack2(agA, g0, g1); unpack2(aoA, o0, o1);
            float cA = sigm(x0 + x1) * tanh_(g0 + g1);
            float hA = sigm(o0 + o1) * tanh_(cA);
            unpack2(aiB, x0, x1); unpack2(agB, g0, g1); unpack2(aoB, o0, o1);
            float cB = sigm(x0 + x1) * tanh_(g0 + g1);
            float hB = sigm(o0 + o1) * tanh_(cB);
            __half2 hh = __floats2half2_rn(hA, hB);
            hn16[j] = *(uint32_t*)&hh;
        }
    }

    /* unpack hn16 -> h2A/h2B (f32 k-pair packing) */
    #pragma unroll
    for (int kp = 0; kp < 32; ++kp) {
        __half2 p0 = *(__half2*)&hn16[2 * kp];
        __half2 p1 = *(__half2*)&hn16[2 * kp + 1];
        float2 f0 = __half22float2(p0);   /* (hA[2kp], hB[2kp]) */
        float2 f1 = __half22float2(p1);
        h2A[kp] = pack2(f0.x, f1.x);
        h2B[kp] = pack2(f0.y, f1.y);
    }

    /* ---------------- layer 2 + fused head ------------------------------ */
    float pmA = 0.f, psA = 0.f, pmB = 0.f, psB = 0.f;
    {
        const float* W = sW + 12288;
        const float* Bb = sB + 192;
        #pragma unroll 1
        for (int j = 0; j < 64; ++j) {
            const ulonglong2* wi = (const ulonglong2*)(W + j * 64);
            const ulonglong2* wg = (const ulonglong2*)(W + (64 + j) * 64);
            const ulonglong2* wo = (const ulonglong2*)(W + (128 + j) * 64);
            u64 aiA = pack2(Bb[j], 0.f),       aiB = aiA;
            u64 agA = pack2(Bb[64 + j], 0.f),  agB = agA;
            u64 aoA = pack2(Bb[128 + j], 0.f), aoB = aoA;
            #pragma unroll
            for (int q = 0; q < 16; ++q) {
                ulonglong2 vi = wi[q], vg = wg[q], vo = wo[q];
                u64 a0 = h2A[2 * q], a1 = h2A[2 * q + 1];
                u64 b0 = h2B[2 * q], b1 = h2B[2 * q + 1];
                aiA = ffma2(vi.x, a0, aiA); aiB = ffma2(vi.x, b0, aiB);
                agA = ffma2(vg.x, a0, agA); agB = ffma2(vg.x, b0, agB);
                aoA = ffma2(vo.x, a0, aoA); aoB = ffma2(vo.x, b0, aoB);
                aiA = ffma2(vi.y, a1, aiA); aiB = ffma2(vi.y, b1, aiB);
                agA = ffma2(vg.y, a1, agA); agB = ffma2(vg.y, b1, agB);
                aoA = ffma2(vo.y, a1, aoA); aoB = ffma2(vo.y, b1, aoB);
            }
            float x0, x1, g0, g1, o0, o1;
            unpack2(aiA, x0, x1); unpack2(agA, g0, g1); unpack2(aoA, o0, o1);
            float cA = sigm(x0 + x1) * tanh_(g0 + g1);
            float hA = sigm(o0 + o1) * tanh_(cA);
            unpack2(aiB, x0, x1); unpack2(agB, g0, g1); unpack2(aoB, o0, o1);
            float cB = sigm(x0 + x1) * tanh_(g0 + g1);
            float hB = sigm(o0 + o1) * tanh_(cB);
            float rA = fmaxf(hA, 0.0f), rB = fmaxf(hB, 0.0f);
            float wm = sWmu[j], ws = sWsg[j];
            pmA = fmaf(rA, wm, pmA); pmB = fmaf(rB, wm, pmB);
            psA = fmaf(rA, ws, psA); psB = fmaf(rB, ws, psB);
        }
    }

    const float bmu = b_mu[0], bsg = b_sigma[0];
    {
        const int n = mA / SEQ_LEN, t = mA % SEQ_LEN;
        out_mu[n * TTOT + t] = pmA + bmu;
        out_sg[n * TTOT + t] = softplus_(psA + bsg) + 1e-6f;
    }
    {
        const int n = mB / SEQ_LEN, t = mB % SEQ_LEN;
        out_mu[n * TTOT + t] = pmB + bmu;
        out_sg[n * TTOT + t] = softplus_(psB + bsg) + 1e-6f;
    }
}

extern "C" void kernel_launch(void* const* d_in, const int* in_sizes, int n_in,
                              void* d_out, int out_size)
{
    const float* X       = (const float*)d_in[0];
    const float* y       = (const float*)d_in[1];
    const float* Xf      = (const float*)d_in[2];
    const float* W_embed = (const float*)d_in[3];
    const float* b_embed = (const float*)d_in[4];
    const float* W_ih    = (const float*)d_in[5];
    const float* b_ih    = (const float*)d_in[6];
    const float* b_hh    = (const float*)d_in[7];
    const float* W_mu    = (const float*)d_in[8];
    const float* b_mu    = (const float*)d_in[9];
    const float* W_sigma = (const float*)d_in[10];
    const float* b_sigma = (const float*)d_in[11];
    float* out = (float*)d_out;

    static bool attr_done = false;
    if (!attr_done) {
        cudaFuncSetAttribute(deepar_v8,
            cudaFuncAttributeMaxDynamicSharedMemorySize, SMEM_TOTAL);
        attr_done = true;
    }

    deepar_v8<<<GRID_B + NCTA_A, BLK, SMEM_TOTAL>>>(
        X, y, Xf, W_embed, b_embed, W_ih, b_ih, b_hh,
        W_mu, b_mu, W_sigma, b_sigma, out);
}